// round 6
// baseline (speedup 1.0000x reference)
#include <cuda_runtime.h>
#include <cuda_fp16.h>
#include <cstdint>

#define BN   2
#define NN   128
#define NP   (NN*NN)          // 16384
#define TOT  (BN*NP)          // 32768
#define KC   131
#define CC   21
#define WW   49
#define NCH  2                // k-chunks

// stage1 tile
#define S1W  16
#define S1H  8
#define S1HW 22
#define S1PX (S1HW*14)        // 308

// stage2 tile
#define T2W  16
#define T2H  8
#define HW2  22
#define HPX  (HW2*14)         // 308
#define CPAD 24

// ---- scratch (static device globals; no runtime allocation) ----
__device__ float g_A[(size_t)NCH*WW*TOT];          // partial A per chunk  ~13MB

// ---------------------------------------------------------------
// stage 1 (tiled, fused exp): per pixel in a 16x8 tile, per k:
//    A[w] += cp[k] * e_w / sum_w e_w ,  e_w = max(Ep*Rq, Eq*Rp)
//    raw integ halo loaded as float, masked, exp'ed into smem as
//    half2(exp(x), exp(-x)); register-prefetched for k+1.
// ---------------------------------------------------------------
__global__ void __launch_bounds__(128, 4)
stage1_kernel(const float* __restrict__ integ,
              const int*   __restrict__ mask,
              const float* __restrict__ cp) {
    __shared__ __half2 sh[2][S1PX];
    __shared__ float   scp[KC];

    int t = threadIdx.x;
    for (int k = t; k < KC; k += 128) scp[k] = cp[k];

    int b     = blockIdx.z & 1;
    int chunk = blockIdx.z >> 1;
    int x0 = blockIdx.x * S1W;
    int y0 = blockIdx.y * S1H;
    int k0 = (chunk * KC) / NCH;
    int k1 = ((chunk + 1) * KC) / NCH;

    int tx = t & 15, ty = t >> 4;

    const float* __restrict__ inb = integ + (size_t)b * KC * NP;
    const int*   __restrict__ mkb = mask  + (size_t)b * NP;
    const __half2 zero = __float2half2_rn(0.0f);

    // this thread's 3 halo fill slots (fixed across k)
    int off0, off1, off2;  bool ok0, ok1, ok2, has2;
    float m0 = 0.f, m1 = 0.f, m2 = 0.f;
    {
        int h0 = t, h1 = t + 128, h2 = t + 256;
        int hy0 = h0 / S1HW, hx0 = h0 - hy0 * S1HW;
        int hy1 = h1 / S1HW, hx1 = h1 - hy1 * S1HW;
        int hy2 = h2 / S1HW, hx2 = h2 - hy2 * S1HW;
        int gy0 = y0 + hy0 - 3, gx0 = x0 + hx0 - 3;
        int gy1 = y0 + hy1 - 3, gx1 = x0 + hx1 - 3;
        int gy2 = y0 + hy2 - 3, gx2 = x0 + hx2 - 3;
        ok0 = ((unsigned)gy0 < NN) && ((unsigned)gx0 < NN);
        ok1 = ((unsigned)gy1 < NN) && ((unsigned)gx1 < NN);
        has2 = (h2 < S1PX);
        ok2 = has2 && ((unsigned)gy2 < NN) && ((unsigned)gx2 < NN);
        off0 = ok0 ? (gy0 * NN + gx0) : 0;
        off1 = ok1 ? (gy1 * NN + gx1) : 0;
        off2 = ok2 ? (gy2 * NN + gx2) : 0;
        if (ok0) m0 = (float)mkb[off0];
        if (ok1) m1 = (float)mkb[off1];
        if (ok2) m2 = (float)mkb[off2];
    }

    float A[50];
    #pragma unroll
    for (int w = 0; w < 50; w++) A[w] = 0.0f;

    // prefetch k0 (raw floats)
    float f0, f1, f2;
    {
        const float* __restrict__ ink = inb + (size_t)k0 * NP;
        f0 = ok0 ? __ldg(ink + off0) : 0.0f;
        f1 = ok1 ? __ldg(ink + off1) : 0.0f;
        f2 = ok2 ? __ldg(ink + off2) : 0.0f;
    }

    for (int k = k0; k < k1; k++) {
        __half2* buf = sh[k & 1];
        {   // masked exp pair, stored as half2 (E, R); OOB slots -> (0,0)
            float x0v = f0 * m0, x1v = f1 * m1, x2v = f2 * m2;
            __half2 e0 = ok0 ? __floats2half2_rn(__expf(x0v), __expf(-x0v)) : zero;
            __half2 e1 = ok1 ? __floats2half2_rn(__expf(x1v), __expf(-x1v)) : zero;
            buf[t]       = e0;
            buf[t + 128] = e1;
            if (has2) {
                __half2 e2 = ok2 ? __floats2half2_rn(__expf(x2v), __expf(-x2v)) : zero;
                buf[t + 256] = e2;
            }
        }
        if (k + 1 < k1) {
            const float* __restrict__ inn = inb + (size_t)(k + 1) * NP;
            f0 = ok0 ? __ldg(inn + off0) : 0.0f;
            f1 = ok1 ? __ldg(inn + off1) : 0.0f;
            f2 = ok2 ? __ldg(inn + off2) : 0.0f;
        }
        __syncthreads();

        const __half2* __restrict__ c00 = buf + ty * S1HW + tx;
        __half2 ct   = c00[3 * S1HW + 3];
        __half2 ctEE = __low2half2(ct);    // (Ep,Ep)
        __half2 ctRR = __high2half2(ct);   // (Rp,Rp)

        __half2 eh[25];
        __half2 es2 = zero;
        #pragma unroll
        for (int pr = 0; pr < 24; pr++) {
            const int wa = 2 * pr, wb = wa + 1;
            __half2 qa = c00[(wa / 7) * S1HW + (wa % 7)];
            __half2 qb = c00[(wb / 7) * S1HW + (wb % 7)];
            __half2 EE = __lows2half2(qa, qb);
            __half2 RR = __highs2half2(qa, qb);
            __half2 e2 = __hmax2(__hmul2(ctEE, RR), __hmul2(EE, ctRR));
            eh[pr] = e2;
            es2 = __hadd2(es2, e2);
        }
        {   // singleton w=48 paired with zero
            __half2 qa = c00[6 * S1HW + 6];
            __half2 EE = __lows2half2(qa, zero);
            __half2 RR = __highs2half2(qa, zero);
            __half2 e2 = __hmax2(__hmul2(ctEE, RR), __hmul2(EE, ctRR));
            eh[24] = e2;
            es2 = __hadd2(es2, e2);
        }
        float esum = __half2float(__hadd(__low2half(es2), __high2half(es2)));
        float s = __fdividef(scp[k], esum);
        #pragma unroll
        for (int pr = 0; pr < 25; pr++) {
            float2 ef = __half22float2(eh[pr]);
            A[2 * pr]     = fmaf(s, ef.x, A[2 * pr]);
            A[2 * pr + 1] = fmaf(s, ef.y, A[2 * pr + 1]);
        }
    }

    int gp = b * NP + (y0 + ty) * NN + (x0 + tx);
    size_t baseA = (size_t)chunk * WW * TOT + gp;
    #pragma unroll
    for (int w = 0; w < WW; w++) g_A[baseA + (size_t)w * TOT] = A[w];
}

// ---------------------------------------------------------------
// stage 2 (tiled + 4-way w-split): out[b,q,c] = sum_w A[p,w]*x2[b,c,p]
//    512 threads/CTA: warp lane-groups handle w-ranges for the same
//    8 output pixels; combined with two shfl_xor butterflies.
// ---------------------------------------------------------------
__global__ void __launch_bounds__(512)
stage2_kernel(const float* __restrict__ x2,
              const int*   __restrict__ mask,
              float*       __restrict__ out) {
    __shared__ float x2s[HPX * CPAD];   // ~29.6 KB
    __shared__ int   msks[HPX];

    int t  = threadIdx.x;
    int b  = blockIdx.z;
    int y0 = blockIdx.y * T2H;
    int x0 = blockIdx.x * T2W;
    const float* __restrict__ x2b = x2 + (size_t)b * CC * NP;

    // fill halo (308 px, one per thread)
    if (t < HPX) {
        int hy = t / HW2, hx = t - hy * HW2;
        int gy = y0 + hy - 3, gx = x0 + hx - 3;
        bool ok = ((unsigned)gy < NN) && ((unsigned)gx < NN);
        int pl = ok ? (gy * NN + gx) : 0;
        int mv = ok ? mask[b * NP + pl] : 0;
        msks[t] = mv;
        #pragma unroll
        for (int c = 0; c < CC; c++)
            x2s[t * CPAD + c] = mv ? x2b[(size_t)c * NP + pl] : 0.0f;
        #pragma unroll
        for (int c = CC; c < CPAD; c++)
            x2s[t * CPAD + c] = 0.0f;
    }
    __syncthreads();

    int lane = t & 31;
    int wid  = t >> 5;               // 0..15
    int wg   = lane >> 3;            // 0..3
    int q    = wid * 8 + (lane & 7); // 0..127
    int tx = q & 15, ty = q >> 4;
    int qy = y0 + ty, qx = x0 + tx;
    int spb = b * NP;

    float acc[CC];
    #pragma unroll
    for (int c = 0; c < CC; c++) acc[c] = 0.0f;

    int wbeg = wg * 13;
    int wend = (wbeg + 13 < WW) ? (wbeg + 13) : WW;

    for (int w = wbeg; w < wend; w++) {
        int di = (w * 37) >> 8;      // w/7 for w in [0,48]
        int dj = w - 7 * di;
        int hy = ty + 6 - di;
        int hx = tx + 6 - dj;
        int h  = hy * HW2 + hx;
        int mv = msks[h];
        int gy = qy + 3 - di, gx = qx + 3 - dj;
        int pl = mv ? (gy * NN + gx) : 0;
        size_t ai = (size_t)w * TOT + spb + pl;
        float a0 = g_A[ai];
        float a1 = g_A[(size_t)WW * TOT + ai];
        float a  = mv ? (a0 + a1) : 0.0f;
        const float4* __restrict__ xv4 = (const float4*)(x2s + h * CPAD);
        #pragma unroll
        for (int j = 0; j < 5; j++) {
            float4 xv = xv4[j];
            acc[4 * j + 0] = fmaf(a, xv.x, acc[4 * j + 0]);
            acc[4 * j + 1] = fmaf(a, xv.y, acc[4 * j + 1]);
            acc[4 * j + 2] = fmaf(a, xv.z, acc[4 * j + 2]);
            acc[4 * j + 3] = fmaf(a, xv.w, acc[4 * j + 3]);
        }
        acc[20] = fmaf(a, x2s[h * CPAD + 20], acc[20]);
    }

    // reduce the 4 w-groups (lanes xor 8 and xor 16)
    #pragma unroll
    for (int c = 0; c < CC; c++)
        acc[c] += __shfl_xor_sync(0xffffffffu, acc[c], 8);
    #pragma unroll
    for (int c = 0; c < CC; c++)
        acc[c] += __shfl_xor_sync(0xffffffffu, acc[c], 16);

    if (wg == 0) {
        float* o = out + (size_t)(spb + qy * NN + qx) * CC;
        #pragma unroll
        for (int c = 0; c < CC; c++) o[c] = acc[c];
    }
}

// ---------------------------------------------------------------
extern "C" void kernel_launch(void* const* d_in, const int* in_sizes, int n_in,
                              void* d_out, int out_size) {
    const float* integ = (const float*)d_in[0];   // [B,K,N,N]
    const float* x2    = (const float*)d_in[1];   // [B,C,N*N]
    const int*   msk   = (const int*)  d_in[2];   // [B,N,N]
    const float* cp    = (const float*)d_in[3];   // [K]
    float* out = (float*)d_out;                   // [B, N*N, C]

    dim3 g1(NN / S1W, NN / S1H, BN * NCH);        // (8,16,4) = 512 CTAs
    stage1_kernel<<<g1, 128>>>(integ, msk, cp);

    dim3 g2(NN / T2W, NN / T2H, BN);              // (8,16,2) = 256 CTAs
    stage2_kernel<<<g2, 512>>>(x2, msk, out);
}

// round 7
// speedup vs baseline: 1.1738x; 1.1738x over previous
#include <cuda_runtime.h>
#include <cuda_fp16.h>
#include <cstdint>

#define BN   2
#define NN   128
#define NP   (NN*NN)          // 16384
#define TOT  (BN*NP)          // 32768
#define KC   131
#define CC   21
#define WW   49
#define NCH  2                // k-chunks

// stage1 tile: 16x8 outputs, 22x14 halo, padded row stride 48 (bank-safe)
#define S1W   16
#define S1H   8
#define S1HW  22
#define S1HH  14
#define S1PX  (S1HW*S1HH)     // 308 logical slots
#define S1STR 48              // padded stride (words)
#define S1BUF (S1STR*S1HH)    // 672 entries per buffer

// stage2 tile
#define T2W  16
#define T2H  8
#define HW2  22
#define HPX  (HW2*14)         // 308
#define CPAD 28               // 28-word px stride: conflict-free float4 LDS

// ---- scratch (static device globals; no runtime allocation) ----
__device__ float g_A[(size_t)NCH*WW*TOT];          // partial A per chunk  ~13MB

// ---------------------------------------------------------------
// stage 1 (tiled, fused exp, bank-safe): per pixel, per k:
//    A[w] += cp[k] * e_w / sum_w e_w ,  e_w = max(Ep*Rq, Eq*Rp)
//    raw integ halo loaded as float, masked, exp'ed into smem as
//    half2(exp(x), exp(-x)); exp for k+1 computed AFTER the window
//    compute so MUFU/LDG latency hides under independent work.
// ---------------------------------------------------------------
__global__ void __launch_bounds__(128, 4)
stage1_kernel(const float* __restrict__ integ,
              const int*   __restrict__ mask,
              const float* __restrict__ cp) {
    __shared__ __half2 sh[2][S1BUF];
    __shared__ float   scp[KC];

    int t = threadIdx.x;
    for (int k = t; k < KC; k += 128) scp[k] = cp[k];

    int b     = blockIdx.z & 1;
    int chunk = blockIdx.z >> 1;
    int x0 = blockIdx.x * S1W;
    int y0 = blockIdx.y * S1H;
    int k0 = (chunk * KC) / NCH;
    int k1 = ((chunk + 1) * KC) / NCH;

    int tx = t & 15, ty = t >> 4;

    const float* __restrict__ inb = integ + (size_t)b * KC * NP;
    const int*   __restrict__ mkb = mask  + (size_t)b * NP;
    const __half2 zero = __float2half2_rn(0.0f);

    // this thread's 3 halo fill slots (fixed across k)
    int off0, off1, off2;          // gmem pixel offsets
    int si0, si1, si2;             // padded smem indices
    bool ok0, ok1, ok2, has2;
    float m0 = 0.f, m1 = 0.f, m2 = 0.f;
    {
        int h0 = t, h1 = t + 128, h2 = t + 256;
        int hy0 = h0 / S1HW, hx0 = h0 - hy0 * S1HW;
        int hy1 = h1 / S1HW, hx1 = h1 - hy1 * S1HW;
        int hy2 = h2 / S1HW, hx2 = h2 - hy2 * S1HW;
        si0 = hy0 * S1STR + hx0;
        si1 = hy1 * S1STR + hx1;
        si2 = hy2 * S1STR + hx2;
        int gy0 = y0 + hy0 - 3, gx0 = x0 + hx0 - 3;
        int gy1 = y0 + hy1 - 3, gx1 = x0 + hx1 - 3;
        int gy2 = y0 + hy2 - 3, gx2 = x0 + hx2 - 3;
        ok0 = ((unsigned)gy0 < NN) && ((unsigned)gx0 < NN);
        ok1 = ((unsigned)gy1 < NN) && ((unsigned)gx1 < NN);
        has2 = (h2 < S1PX);
        ok2 = has2 && ((unsigned)gy2 < NN) && ((unsigned)gx2 < NN);
        off0 = ok0 ? (gy0 * NN + gx0) : 0;
        off1 = ok1 ? (gy1 * NN + gx1) : 0;
        off2 = ok2 ? (gy2 * NN + gx2) : 0;
        if (ok0) m0 = (float)mkb[off0];
        if (ok1) m1 = (float)mkb[off1];
        if (ok2) m2 = (float)mkb[off2];
    }

    float A[WW];
    #pragma unroll
    for (int w = 0; w < WW; w++) A[w] = 0.0f;

    // prefetch + exp for k0
    __half2 e0, e1, e2;
    {
        const float* __restrict__ ink = inb + (size_t)k0 * NP;
        float f0 = ok0 ? __ldg(ink + off0) : 0.0f;
        float f1 = ok1 ? __ldg(ink + off1) : 0.0f;
        float f2 = ok2 ? __ldg(ink + off2) : 0.0f;
        float v0 = f0 * m0, v1 = f1 * m1, v2 = f2 * m2;
        e0 = ok0 ? __floats2half2_rn(__expf(v0), __expf(-v0)) : zero;
        e1 = ok1 ? __floats2half2_rn(__expf(v1), __expf(-v1)) : zero;
        e2 = ok2 ? __floats2half2_rn(__expf(v2), __expf(-v2)) : zero;
    }

    for (int k = k0; k < k1; k++) {
        __half2* buf = sh[k & 1];
        buf[si0] = e0;
        buf[si1] = e1;
        if (has2) buf[si2] = e2;

        // issue next-k loads early (consumed after the window compute)
        float f0 = 0.f, f1 = 0.f, f2 = 0.f;
        if (k + 1 < k1) {
            const float* __restrict__ inn = inb + (size_t)(k + 1) * NP;
            f0 = ok0 ? __ldg(inn + off0) : 0.0f;
            f1 = ok1 ? __ldg(inn + off1) : 0.0f;
            f2 = ok2 ? __ldg(inn + off2) : 0.0f;
        }
        __syncthreads();

        const __half2* __restrict__ c00 = buf + ty * S1STR + tx;
        __half2 ct   = c00[3 * S1STR + 3];
        __half2 ctEE = __low2half2(ct);    // (Ep,Ep)
        __half2 ctRR = __high2half2(ct);   // (Rp,Rp)

        __half2 eh[25];
        __half2 esa = zero, esb = zero, esc = zero, esd = zero;
        #pragma unroll
        for (int pr = 0; pr < 24; pr++) {
            const int wa = 2 * pr, wb = wa + 1;
            __half2 qa = c00[(wa / 7) * S1STR + (wa % 7)];
            __half2 qb = c00[(wb / 7) * S1STR + (wb % 7)];
            __half2 EE = __lows2half2(qa, qb);
            __half2 RR = __highs2half2(qa, qb);
            __half2 ew = __hmax2(__hmul2(ctEE, RR), __hmul2(EE, ctRR));
            eh[pr] = ew;
            if ((pr & 3) == 0)      esa = __hadd2(esa, ew);
            else if ((pr & 3) == 1) esb = __hadd2(esb, ew);
            else if ((pr & 3) == 2) esc = __hadd2(esc, ew);
            else                    esd = __hadd2(esd, ew);
        }
        {   // singleton w=48 paired with zero
            __half2 qa = c00[6 * S1STR + 6];
            __half2 EE = __lows2half2(qa, zero);
            __half2 RR = __highs2half2(qa, zero);
            __half2 ew = __hmax2(__hmul2(ctEE, RR), __hmul2(EE, ctRR));
            eh[24] = ew;
            esa = __hadd2(esa, ew);
        }
        __half2 es2 = __hadd2(__hadd2(esa, esb), __hadd2(esc, esd));
        float esum = __half2float(__hadd(__low2half(es2), __high2half(es2)));
        float s = __fdividef(scp[k], esum);
        #pragma unroll
        for (int pr = 0; pr < 24; pr++) {
            float2 ef = __half22float2(eh[pr]);
            A[2 * pr]     = fmaf(s, ef.x, A[2 * pr]);
            A[2 * pr + 1] = fmaf(s, ef.y, A[2 * pr + 1]);
        }
        A[48] = fmaf(s, __half2float(__low2half(eh[24])), A[48]);

        // exp for k+1 (MUFU hidden behind other warps' window work)
        if (k + 1 < k1) {
            float v0 = f0 * m0, v1 = f1 * m1, v2 = f2 * m2;
            e0 = ok0 ? __floats2half2_rn(__expf(v0), __expf(-v0)) : zero;
            e1 = ok1 ? __floats2half2_rn(__expf(v1), __expf(-v1)) : zero;
            e2 = ok2 ? __floats2half2_rn(__expf(v2), __expf(-v2)) : zero;
        }
    }

    int gp = b * NP + (y0 + ty) * NN + (x0 + tx);
    size_t baseA = (size_t)chunk * WW * TOT + gp;
    #pragma unroll
    for (int w = 0; w < WW; w++) g_A[baseA + (size_t)w * TOT] = A[w];
}

// ---------------------------------------------------------------
// stage 2 (tiled + 4-way w-split): out[b,q,c] = sum_w A[p,w]*x2[b,c,p]
//    512 threads/CTA; px stride 28 words in smem -> conflict-free
//    float4 reads; combined with two shfl_xor butterflies.
// ---------------------------------------------------------------
__global__ void __launch_bounds__(512)
stage2_kernel(const float* __restrict__ x2,
              const int*   __restrict__ mask,
              float*       __restrict__ out) {
    __shared__ float x2s[HPX * CPAD];   // ~34.5 KB
    __shared__ int   msks[HPX];

    int t  = threadIdx.x;
    int b  = blockIdx.z;
    int y0 = blockIdx.y * T2H;
    int x0 = blockIdx.x * T2W;
    const float* __restrict__ x2b = x2 + (size_t)b * CC * NP;

    // fill halo (308 px, one per thread)
    if (t < HPX) {
        int hy = t / HW2, hx = t - hy * HW2;
        int gy = y0 + hy - 3, gx = x0 + hx - 3;
        bool ok = ((unsigned)gy < NN) && ((unsigned)gx < NN);
        int pl = ok ? (gy * NN + gx) : 0;
        int mv = ok ? mask[b * NP + pl] : 0;
        msks[t] = mv;
        #pragma unroll
        for (int c = 0; c < CC; c++)
            x2s[t * CPAD + c] = mv ? x2b[(size_t)c * NP + pl] : 0.0f;
        #pragma unroll
        for (int c = CC; c < CPAD; c++)
            x2s[t * CPAD + c] = 0.0f;
    }
    __syncthreads();

    int lane = t & 31;
    int wid  = t >> 5;               // 0..15
    int wg   = lane >> 3;            // 0..3
    int q    = wid * 8 + (lane & 7); // 0..127
    int tx = q & 15, ty = q >> 4;
    int qy = y0 + ty, qx = x0 + tx;
    int spb = b * NP;

    float acc[CC];
    #pragma unroll
    for (int c = 0; c < CC; c++) acc[c] = 0.0f;

    int wbeg = wg * 13;
    int wend = (wbeg + 13 < WW) ? (wbeg + 13) : WW;

    for (int w = wbeg; w < wend; w++) {
        int di = (w * 37) >> 8;      // w/7 for w in [0,48]
        int dj = w - 7 * di;
        int hy = ty + 6 - di;
        int hx = tx + 6 - dj;
        int h  = hy * HW2 + hx;
        int mv = msks[h];
        int gy = qy + 3 - di, gx = qx + 3 - dj;
        int pl = mv ? (gy * NN + gx) : 0;
        size_t ai = (size_t)w * TOT + spb + pl;
        float a0 = g_A[ai];
        float a1 = g_A[(size_t)WW * TOT + ai];
        float a  = mv ? (a0 + a1) : 0.0f;
        const float4* __restrict__ xv4 = (const float4*)(x2s + h * CPAD);
        #pragma unroll
        for (int j = 0; j < 5; j++) {
            float4 xv = xv4[j];
            acc[4 * j + 0] = fmaf(a, xv.x, acc[4 * j + 0]);
            acc[4 * j + 1] = fmaf(a, xv.y, acc[4 * j + 1]);
            acc[4 * j + 2] = fmaf(a, xv.z, acc[4 * j + 2]);
            acc[4 * j + 3] = fmaf(a, xv.w, acc[4 * j + 3]);
        }
        acc[20] = fmaf(a, x2s[h * CPAD + 20], acc[20]);
    }

    // reduce the 4 w-groups (lanes xor 8 and xor 16)
    #pragma unroll
    for (int c = 0; c < CC; c++)
        acc[c] += __shfl_xor_sync(0xffffffffu, acc[c], 8);
    #pragma unroll
    for (int c = 0; c < CC; c++)
        acc[c] += __shfl_xor_sync(0xffffffffu, acc[c], 16);

    if (wg == 0) {
        float* o = out + (size_t)(spb + qy * NN + qx) * CC;
        #pragma unroll
        for (int c = 0; c < CC; c++) o[c] = acc[c];
    }
}

// ---------------------------------------------------------------
extern "C" void kernel_launch(void* const* d_in, const int* in_sizes, int n_in,
                              void* d_out, int out_size) {
    const float* integ = (const float*)d_in[0];   // [B,K,N,N]
    const float* x2    = (const float*)d_in[1];   // [B,C,N*N]
    const int*   msk   = (const int*)  d_in[2];   // [B,N,N]
    const float* cp    = (const float*)d_in[3];   // [K]
    float* out = (float*)d_out;                   // [B, N*N, C]

    dim3 g1(NN / S1W, NN / S1H, BN * NCH);        // (8,16,4) = 512 CTAs
    stage1_kernel<<<g1, 128>>>(integ, msk, cp);

    dim3 g2(NN / T2W, NN / T2H, BN);              // (8,16,2) = 256 CTAs
    stage2_kernel<<<g2, 512>>>(x2, msk, out);
}